// round 3
// baseline (speedup 1.0000x reference)
#include <cuda_runtime.h>
#include <math.h>

// ---------------- problem constants ----------------
#define SEQ   2048
#define DIM   1024
#define NH    16
#define HD    64
#define NEXP  32
#define ED    128
#define TOPK  8
#define DSH   2048
#define EPS   1e-6f
#define RSF   2.5f

// ---------------- scratch (device globals; no allocation allowed) ----------------
__device__ float g_xnorm[SEQ * DIM];
__device__ float g_qkv[SEQ * 3 * DIM];
__device__ float g_q[NH * SEQ * HD];
__device__ float g_k[NH * SEQ * HD];
__device__ float g_v[NH * SEQ * HD];
__device__ float g_attn[SEQ * DIM];
__device__ float g_ffninput[SEQ * DIM];
__device__ float g_xffn[SEQ * DIM];
__device__ float g_logits[SEQ * NEXP];
__device__ float g_gates[SEQ * TOPK];
__device__ float g_y[SEQ * DIM];          // moe out + ffn residual
__device__ float g_up[SEQ * 2 * DSH];
__device__ float g_act[SEQ * DSH];

// ---------------- rmsnorm: one block per row ----------------
__global__ void rmsnorm_kernel(const float* __restrict__ x,
                               const float* __restrict__ w,
                               float* __restrict__ out) {
    int t = blockIdx.x;
    int tid = threadIdx.x;               // 256
    const float* xr = x + (size_t)t * DIM;
    float vals[4];
    float s = 0.f;
#pragma unroll
    for (int i = 0; i < 4; i++) {
        float v = xr[tid + i * 256];
        vals[i] = v;
        s += v * v;
    }
#pragma unroll
    for (int o = 16; o > 0; o >>= 1) s += __shfl_xor_sync(0xffffffffu, s, o);
    __shared__ float red[8];
    int warp = tid >> 5;
    if ((tid & 31) == 0) red[warp] = s;
    __syncthreads();
    if (tid == 0) {
        float tot = 0.f;
#pragma unroll
        for (int i = 0; i < 8; i++) tot += red[i];
        red[0] = 1.f / sqrtf(tot / (float)DIM + EPS);
    }
    __syncthreads();
    float sc = red[0];
    float* orow = out + (size_t)t * DIM;
#pragma unroll
    for (int i = 0; i < 4; i++) {
        int c = tid + i * 256;
        orow[c] = vals[i] * sc * w[c];
    }
}

// ---------------- tiled fp32 GEMM: C = A[MxK] * B[KxN] (+res) ----------------
// BM=BN=64, BK=16, 256 threads, 4x4 microtile. M,K multiples required; N guarded.
#define BM 64
#define BN 64
#define BK 16
__global__ void sgemm_kernel(const float* __restrict__ A,
                             const float* __restrict__ B,
                             float* __restrict__ C,
                             const float* __restrict__ res,
                             int M, int N, int Kd) {
    __shared__ float As[BK][BM];
    __shared__ float Bs[BK][BN];
    int tid = threadIdx.x;
    int bx = blockIdx.x, by = blockIdx.y;
    int tx = tid & 15, ty = tid >> 4;
    int row0 = by * BM + ty * 4;
    int col0 = bx * BN + tx * 4;
    float acc[4][4] = {};
    int ar = tid >> 2, ac = (tid & 3) * 4;   // A tile: row ar (0..63), cols ac..ac+3
    int br = tid >> 4, bc = (tid & 15) * 4;  // B tile: row br (0..15), cols bc..bc+3

    for (int k0 = 0; k0 < Kd; k0 += BK) {
        float4 av = *(const float4*)&A[(size_t)(by * BM + ar) * Kd + k0 + ac];
        As[ac + 0][ar] = av.x;
        As[ac + 1][ar] = av.y;
        As[ac + 2][ar] = av.z;
        As[ac + 3][ar] = av.w;
        float4 bv = make_float4(0.f, 0.f, 0.f, 0.f);
        int bcol = bx * BN + bc;
        if (bcol < N) bv = *(const float4*)&B[(size_t)(k0 + br) * N + bcol];
        *(float4*)&Bs[br][bc] = bv;
        __syncthreads();
#pragma unroll
        for (int kk = 0; kk < BK; kk++) {
            float4 a4 = *(float4*)&As[kk][ty * 4];
            float4 b4 = *(float4*)&Bs[kk][tx * 4];
            float a[4] = {a4.x, a4.y, a4.z, a4.w};
            float b[4] = {b4.x, b4.y, b4.z, b4.w};
#pragma unroll
            for (int i = 0; i < 4; i++)
#pragma unroll
                for (int j = 0; j < 4; j++) acc[i][j] += a[i] * b[j];
        }
        __syncthreads();
    }
#pragma unroll
    for (int i = 0; i < 4; i++) {
        int r = row0 + i;
#pragma unroll
        for (int j = 0; j < 4; j++) {
            int c = col0 + j;
            if (c < N) {
                float v = acc[i][j];
                if (res) v += res[(size_t)r * N + c];
                C[(size_t)r * N + c] = v;
            }
        }
    }
}

// ---------------- q/k l2norm + rope, v passthrough ----------------
// grid (NH, SEQ), 64 threads
__global__ void qkprep_kernel(const float* __restrict__ qkv,
                              float* __restrict__ q,
                              float* __restrict__ k,
                              float* __restrict__ v) {
    int h = blockIdx.x;
    int s = blockIdx.y;
    int d = threadIdx.x;                 // 0..63
    size_t base_in = (size_t)s * (3 * DIM) + h * HD + d;
    float qv = qkv[base_in];
    float kv = qkv[base_in + DIM];
    float vv = qkv[base_in + 2 * DIM];

    float sq = qv * qv, sk = kv * kv;
#pragma unroll
    for (int o = 16; o > 0; o >>= 1) {
        sq += __shfl_xor_sync(0xffffffffu, sq, o);
        sk += __shfl_xor_sync(0xffffffffu, sk, o);
    }
    __shared__ float pq[2], pk[2];
    __shared__ float sqm[64], skm[64];
    int w = d >> 5;
    if ((d & 31) == 0) { pq[w] = sq; pk[w] = sk; }
    __syncthreads();
    float nq = sqrtf(pq[0] + pq[1]);
    float nk = sqrtf(pk[0] + pk[1]);
    float qn = qv / fmaxf(nq, EPS);
    float kn = kv / fmaxf(nk, EPS);
    sqm[d] = qn;
    skm[d] = kn;
    __syncthreads();

    int i = d & 31;
    bool lo = d < 32;
    float inv = powf(1.0f / 10000.0f, (float)(2 * i) / 64.0f);
    float f = (float)s * inv;
    float c = cosf(f), sn = sinf(f);
    float q1 = sqm[i], q2 = sqm[i + 32];
    float k1 = skm[i], k2 = skm[i + 32];
    float oq = lo ? (q1 * c + q2 * sn) : (-q1 * sn + q2 * c);
    float ok = lo ? (k1 * c + k2 * sn) : (-k1 * sn + k2 * c);

    size_t base_out = ((size_t)h * SEQ + s) * HD + d;
    q[base_out] = oq;
    k[base_out] = ok;
    v[base_out] = vv;
}

// ---------------- causal attention: one warp per query row ----------------
// grid NH*(SEQ/8), 256 threads (8 warps = 8 queries); smem K/V tiles of 32 keys
__global__ void attn_kernel(const float* __restrict__ Q,
                            const float* __restrict__ Kt,
                            const float* __restrict__ Vt,
                            float* __restrict__ out) {
    const int QPB = 8;
    int h = blockIdx.x / (SEQ / QPB);
    int qb = blockIdx.x % (SEQ / QPB);
    int tid = threadIdx.x;
    int w = tid >> 5, lane = tid & 31;
    int qi = qb * QPB + w;

    const float* qrow = Q + ((size_t)h * SEQ + qi) * HD;
    float q[HD];
#pragma unroll
    for (int d = 0; d < HD; d++) q[d] = qrow[d];

    __shared__ float Ks[32][HD + 1];
    __shared__ float Vs[32][HD + 1];

    float m = -1e30f, l = 0.f, acc0 = 0.f, acc1 = 0.f;
    int d0 = lane, d1 = lane + 32;
    int qmax = qb * QPB + (QPB - 1);
    int ntiles = qmax / 32 + 1;
    const float scale = 0.125f;  // 1/sqrt(64)

    for (int kb = 0; kb < ntiles; kb++) {
        const float* kbase = Kt + ((size_t)h * SEQ + kb * 32) * HD;
        const float* vbase = Vt + ((size_t)h * SEQ + kb * 32) * HD;
        for (int idx = tid; idx < 32 * HD; idx += 256) {
            int j = idx >> 6, d = idx & 63;
            Ks[j][d] = kbase[idx];
            Vs[j][d] = vbase[idx];
        }
        __syncthreads();
        if (kb * 32 <= qi) {
            int key = kb * 32 + lane;
            float s;
            if (key <= qi) {
                s = 0.f;
#pragma unroll
                for (int d = 0; d < HD; d++) s += q[d] * Ks[lane][d];
                s *= scale;
            } else {
                s = -1e30f;
            }
            float tm = s;
#pragma unroll
            for (int o = 16; o > 0; o >>= 1)
                tm = fmaxf(tm, __shfl_xor_sync(0xffffffffu, tm, o));
            float mnew = fmaxf(m, tm);
            float corr = expf(m - mnew);
            float p = expf(s - mnew);
            float psum = p;
#pragma unroll
            for (int o = 16; o > 0; o >>= 1)
                psum += __shfl_xor_sync(0xffffffffu, psum, o);
            l = l * corr + psum;
            acc0 *= corr;
            acc1 *= corr;
#pragma unroll
            for (int jj = 0; jj < 32; jj++) {
                float pj = __shfl_sync(0xffffffffu, p, jj);
                acc0 += pj * Vs[jj][d0];
                acc1 += pj * Vs[jj][d1];
            }
            m = mnew;
        }
        __syncthreads();
    }
    float inv_l = 1.f / l;
    size_t ob = (size_t)qi * DIM + h * HD;
    out[ob + d0] = acc0 * inv_l;
    out[ob + d1] = acc1 * inv_l;
}

// ---------------- gates ----------------
__global__ void gates_kernel(const float* __restrict__ logits,
                             const int* __restrict__ indices,
                             const float* __restrict__ values,
                             float* __restrict__ gates) {
    int i = blockIdx.x * blockDim.x + threadIdx.x;
    if (i < SEQ * TOPK) {
        int t = i / TOPK;
        int idx = indices[i];
        float v = values[i] + logits[t * NEXP + idx];
        gates[i] = RSF / (1.f + expf(-v));
    }
}

// ---------------- MoE: one block (128 threads) per token, loop over 8 slots ----------------
__global__ void moe_kernel(const float* __restrict__ xffn,
                           const int* __restrict__ indices,
                           const float* __restrict__ gates,
                           const float* __restrict__ experts,
                           const float* __restrict__ ffninput,
                           float* __restrict__ y) {
    int t = blockIdx.x;
    int tid = threadIdx.x;               // 128
    __shared__ float xs[DIM];
    __shared__ float hs[ED];
    for (int i = tid; i < DIM; i += 128) xs[i] = xffn[(size_t)t * DIM + i];
    float yacc[8] = {};
    __syncthreads();

    const size_t MAT = (size_t)NEXP * DIM * ED;
    for (int k = 0; k < TOPK; k++) {
        int e = indices[t * TOPK + k];
        float gate = gates[t * TOPK + k];
        const float* W0 = experts + (size_t)e * DIM * ED;
        const float* W1 = experts + MAT + (size_t)e * DIM * ED;
        float g = 0.f, u = 0.f;
#pragma unroll 4
        for (int d = 0; d < DIM; d++) {
            float xv = xs[d];
            g += xv * W0[(size_t)d * ED + tid];
            u += xv * W1[(size_t)d * ED + tid];
        }
        float hval = (g / (1.f + expf(-g))) * u * gate;
        hs[tid] = hval;
        __syncthreads();
        const float* W2 = experts + 2 * MAT + (size_t)e * DIM * ED;
#pragma unroll
        for (int j = 0; j < 8; j++) {
            int d = tid * 8 + j;
            const float* wrow = W2 + (size_t)d * ED;
            float s = 0.f;
#pragma unroll
            for (int h4 = 0; h4 < ED; h4 += 4) {
                float4 wv = *(const float4*)&wrow[h4];
                s += hs[h4] * wv.x + hs[h4 + 1] * wv.y +
                     hs[h4 + 2] * wv.z + hs[h4 + 3] * wv.w;
            }
            yacc[j] += s;
        }
        __syncthreads();
    }
#pragma unroll
    for (int j = 0; j < 8; j++) {
        size_t o = (size_t)t * DIM + tid * 8 + j;
        y[o] = yacc[j] + ffninput[o];   // fold in residual for final epilogue
    }
}

// ---------------- swiglu on shared-expert up projection ----------------
__global__ void swiglu_kernel(const float* __restrict__ up, float* __restrict__ act) {
    int i = blockIdx.x * blockDim.x + threadIdx.x;
    if (i < SEQ * DSH) {
        int t = i / DSH, j = i % DSH;
        float x1 = up[(size_t)t * (2 * DSH) + j];
        float x2 = up[(size_t)t * (2 * DSH) + DSH + j];
        act[i] = (x1 / (1.f + expf(-x1))) * x2;
    }
}

// ---------------- launch ----------------
extern "C" void kernel_launch(void* const* d_in, const int* in_sizes, int n_in,
                              void* d_out, int out_size) {
    const float* x_input     = (const float*)d_in[0];
    const int*   indices     = (const int*)d_in[1];
    const float* values      = (const float*)d_in[2];
    const float* w_attn      = (const float*)d_in[3];
    const float* w_attn_o    = (const float*)d_in[4];
    const float* attn_norm_w = (const float*)d_in[5];
    const float* ffn_norm_w  = (const float*)d_in[6];
    const float* ffn_experts = (const float*)d_in[7];
    const float* keys_w      = (const float*)d_in[8];
    const float* w_up        = (const float*)d_in[9];
    const float* w_down      = (const float*)d_in[10];
    float* out = (float*)d_out;

    float *p_xnorm, *p_qkv, *p_q, *p_k, *p_v, *p_attn, *p_ffninput, *p_xffn;
    float *p_logits, *p_gates, *p_y, *p_upb, *p_act;
    cudaGetSymbolAddress((void**)&p_xnorm, g_xnorm);
    cudaGetSymbolAddress((void**)&p_qkv, g_qkv);
    cudaGetSymbolAddress((void**)&p_q, g_q);
    cudaGetSymbolAddress((void**)&p_k, g_k);
    cudaGetSymbolAddress((void**)&p_v, g_v);
    cudaGetSymbolAddress((void**)&p_attn, g_attn);
    cudaGetSymbolAddress((void**)&p_ffninput, g_ffninput);
    cudaGetSymbolAddress((void**)&p_xffn, g_xffn);
    cudaGetSymbolAddress((void**)&p_logits, g_logits);
    cudaGetSymbolAddress((void**)&p_gates, g_gates);
    cudaGetSymbolAddress((void**)&p_y, g_y);
    cudaGetSymbolAddress((void**)&p_upb, g_up);
    cudaGetSymbolAddress((void**)&p_act, g_act);

    dim3 b256(256);

    // 1. attn rmsnorm
    rmsnorm_kernel<<<SEQ, b256>>>(x_input, attn_norm_w, p_xnorm);
    // 2. qkv projection
    {
        dim3 grid((3 * DIM) / BN, SEQ / BM);
        sgemm_kernel<<<grid, b256>>>(p_xnorm, w_attn, p_qkv, nullptr, SEQ, 3 * DIM, DIM);
    }
    // 3. l2norm + rope
    {
        dim3 grid(NH, SEQ);
        qkprep_kernel<<<grid, 64>>>(p_qkv, p_q, p_k, p_v);
    }
    // 4. causal attention
    attn_kernel<<<NH * (SEQ / 8), b256>>>(p_q, p_k, p_v, p_attn);
    // 5. output projection + residual
    {
        dim3 grid(DIM / BN, SEQ / BM);
        sgemm_kernel<<<grid, b256>>>(p_attn, w_attn_o, p_ffninput, x_input, SEQ, DIM, DIM);
    }
    // 6. ffn rmsnorm
    rmsnorm_kernel<<<SEQ, b256>>>(p_ffninput, ffn_norm_w, p_xffn);
    // 7. router logits
    {
        dim3 grid((NEXP + BN - 1) / BN, SEQ / BM);
        sgemm_kernel<<<grid, b256>>>(p_xffn, keys_w, p_logits, nullptr, SEQ, NEXP, DIM);
    }
    // 8. gates
    gates_kernel<<<(SEQ * TOPK + 255) / 256, b256>>>(p_logits, indices, values, p_gates);
    // 9. MoE (+ffn residual folded in)
    moe_kernel<<<SEQ, 128>>>(p_xffn, indices, p_gates, ffn_experts, p_ffninput, p_y);
    // 10. shared expert up
    {
        dim3 grid((2 * DSH) / BN, SEQ / BM);
        sgemm_kernel<<<grid, b256>>>(p_xffn, w_up, p_upb, nullptr, SEQ, 2 * DSH, DIM);
    }
    // 11. swiglu
    swiglu_kernel<<<(SEQ * DSH + 255) / 256, b256>>>(p_upb, p_act);
    // 12. shared expert down + (moe+residual) epilogue -> final output
    {
        dim3 grid(DIM / BN, SEQ / BM);
        sgemm_kernel<<<grid, b256>>>(p_act, w_down, out, p_y, SEQ, DIM, DSH);
    }
}

// round 8
// speedup vs baseline: 3.3413x; 3.3413x over previous
#include <cuda_runtime.h>
#include <math.h>

// ---------------- problem constants ----------------
#define SEQ   2048
#define DIM   1024
#define NH    16
#define HD    64
#define NEXP  32
#define ED    128
#define TOPK  8
#define DSH   2048
#define EPS   1e-6f
#define RSF   2.5f

#define NSLOT (SEQ * TOPK)   // 16384 assignments

// ---------------- scratch (device globals; no allocation allowed) ----------------
__device__ float g_xnorm[SEQ * DIM];
__device__ float g_qkv[SEQ * 3 * DIM];
__device__ float g_q[NH * SEQ * HD];
__device__ float g_k[NH * SEQ * HD];
__device__ float g_v[NH * SEQ * HD];
__device__ float g_attn[SEQ * DIM];
__device__ float g_ffninput[SEQ * DIM];
__device__ float g_xffn[SEQ * DIM];
__device__ float g_logits[SEQ * NEXP];
__device__ float g_gates[NSLOT];
__device__ float g_y[SEQ * DIM];
__device__ float g_up[SEQ * 2 * DSH];
__device__ float g_act[SEQ * DSH];

// MoE grouped-GEMM scratch
__device__ int   g_cnt[NEXP];
__device__ int   g_off[NEXP];
__device__ int   g_cur[NEXP];
__device__ int   g_perm[NSLOT];      // slot -> token
__device__ int   g_slot_of[NSLOT];   // (t,k) -> slot
__device__ float g_gatep[NSLOT];     // slot -> gate
__device__ float g_Gbuf[NSLOT * ED];     // 8 MB
__device__ float g_Hbuf[NSLOT * ED];     // 8 MB
__device__ float g_slotbuf[NSLOT * DIM]; // 64 MB

// ---------------- rmsnorm: one block per row ----------------
__global__ void rmsnorm_kernel(const float* __restrict__ x,
                               const float* __restrict__ w,
                               float* __restrict__ out) {
    int t = blockIdx.x;
    int tid = threadIdx.x;               // 256
    const float* xr = x + (size_t)t * DIM;
    float vals[4];
    float s = 0.f;
#pragma unroll
    for (int i = 0; i < 4; i++) {
        float v = xr[tid + i * 256];
        vals[i] = v;
        s += v * v;
    }
#pragma unroll
    for (int o = 16; o > 0; o >>= 1) s += __shfl_xor_sync(0xffffffffu, s, o);
    __shared__ float red[8];
    int warp = tid >> 5;
    if ((tid & 31) == 0) red[warp] = s;
    __syncthreads();
    if (tid == 0) {
        float tot = 0.f;
#pragma unroll
        for (int i = 0; i < 8; i++) tot += red[i];
        red[0] = 1.f / sqrtf(tot / (float)DIM + EPS);
    }
    __syncthreads();
    float sc = red[0];
    float* orow = out + (size_t)t * DIM;
#pragma unroll
    for (int i = 0; i < 4; i++) {
        int c = tid + i * 256;
        orow[c] = vals[i] * sc * w[c];
    }
}

// ---------------- small guarded GEMM (router only): 64x64x16 ----------------
#define BM 64
#define BN 64
#define BK 16
__global__ void sgemm_kernel(const float* __restrict__ A,
                             const float* __restrict__ B,
                             float* __restrict__ C,
                             const float* __restrict__ res,
                             int M, int N, int Kd) {
    __shared__ float As[BK][BM];
    __shared__ float Bs[BK][BN];
    int tid = threadIdx.x;
    int bx = blockIdx.x, by = blockIdx.y;
    int tx = tid & 15, ty = tid >> 4;
    int row0 = by * BM + ty * 4;
    int col0 = bx * BN + tx * 4;
    float acc[4][4] = {};
    int ar = tid >> 2, ac = (tid & 3) * 4;
    int br = tid >> 4, bc = (tid & 15) * 4;

    for (int k0 = 0; k0 < Kd; k0 += BK) {
        float4 av = *(const float4*)&A[(size_t)(by * BM + ar) * Kd + k0 + ac];
        As[ac + 0][ar] = av.x;
        As[ac + 1][ar] = av.y;
        As[ac + 2][ar] = av.z;
        As[ac + 3][ar] = av.w;
        float4 bv = make_float4(0.f, 0.f, 0.f, 0.f);
        int bcol = bx * BN + bc;
        if (bcol < N) bv = *(const float4*)&B[(size_t)(k0 + br) * N + bcol];
        *(float4*)&Bs[br][bc] = bv;
        __syncthreads();
#pragma unroll
        for (int kk = 0; kk < BK; kk++) {
            float4 a4 = *(float4*)&As[kk][ty * 4];
            float4 b4 = *(float4*)&Bs[kk][tx * 4];
            float a[4] = {a4.x, a4.y, a4.z, a4.w};
            float b[4] = {b4.x, b4.y, b4.z, b4.w};
#pragma unroll
            for (int i = 0; i < 4; i++)
#pragma unroll
                for (int j = 0; j < 4; j++) acc[i][j] += a[i] * b[j];
        }
        __syncthreads();
    }
#pragma unroll
    for (int i = 0; i < 4; i++) {
        int r = row0 + i;
#pragma unroll
        for (int j = 0; j < 4; j++) {
            int c = col0 + j;
            if (c < N) {
                float v = acc[i][j];
                if (res) v += res[(size_t)r * N + c];
                C[(size_t)r * N + c] = v;
            }
        }
    }
}

// ---------------- fast fp32 GEMM: 128x128 block tile, 8x8 micro, BK=8 ----------
// Requires M%128==0, N%128==0, K%8==0 (all dense uses satisfy this).
#define GBM 128
#define GBN 128
#define GBK 8
__global__ __launch_bounds__(256) void sgemm128_kernel(
    const float* __restrict__ A, const float* __restrict__ B,
    float* __restrict__ C, const float* __restrict__ res,
    int N, int K) {
    __shared__ float As[GBK][GBM];
    __shared__ float Bs[GBK][GBN];
    int tid = threadIdx.x;
    int bx = blockIdx.x, by = blockIdx.y;

    int arow = tid >> 1;            // 0..127
    int acol = (tid & 1) << 2;      // 0/4
    int brow = tid >> 5;            // 0..7
    int bcol = (tid & 31) << 2;     // 0..124
    int tx = tid & 15, ty = tid >> 4;

    const float* Abase = A + (size_t)(by * GBM + arow) * K + acol;
    const float* Bbase = B + (size_t)brow * N + bx * GBN + bcol;

    float acc[8][8] = {};
    float4 av = *(const float4*)Abase;
    float4 bv = *(const float4*)Bbase;

    for (int k0 = 0; k0 < K; k0 += GBK) {
        As[acol + 0][arow] = av.x;
        As[acol + 1][arow] = av.y;
        As[acol + 2][arow] = av.z;
        As[acol + 3][arow] = av.w;
        *(float4*)&Bs[brow][bcol] = bv;
        __syncthreads();
        if (k0 + GBK < K) {
            av = *(const float4*)(Abase + k0 + GBK);
            bv = *(const float4*)(Bbase + (size_t)(k0 + GBK) * N);
        }
#pragma unroll
        for (int kk = 0; kk < GBK; kk++) {
            float a[8], b[8];
            *(float4*)(a)     = *(float4*)&As[kk][ty * 8];
            *(float4*)(a + 4) = *(float4*)&As[kk][ty * 8 + 4];
            *(float4*)(b)     = *(float4*)&Bs[kk][tx * 8];
            *(float4*)(b + 4) = *(float4*)&Bs[kk][tx * 8 + 4];
#pragma unroll
            for (int i = 0; i < 8; i++)
#pragma unroll
                for (int j = 0; j < 8; j++) acc[i][j] += a[i] * b[j];
        }
        __syncthreads();
    }
#pragma unroll
    for (int i = 0; i < 8; i++) {
        size_t row = (size_t)by * GBM + ty * 8 + i;
        float* crow = C + row * N + bx * GBN + tx * 8;
        float4 v0 = make_float4(acc[i][0], acc[i][1], acc[i][2], acc[i][3]);
        float4 v1 = make_float4(acc[i][4], acc[i][5], acc[i][6], acc[i][7]);
        if (res) {
            const float* rrow = res + row * N + bx * GBN + tx * 8;
            float4 r0 = *(const float4*)rrow;
            float4 r1 = *(const float4*)(rrow + 4);
            v0.x += r0.x; v0.y += r0.y; v0.z += r0.z; v0.w += r0.w;
            v1.x += r1.x; v1.y += r1.y; v1.z += r1.z; v1.w += r1.w;
        }
        *(float4*)crow = v0;
        *(float4*)(crow + 4) = v1;
    }
}

// ---------------- q/k l2norm + rope, v passthrough ----------------
__global__ void qkprep_kernel(const float* __restrict__ qkv,
                              float* __restrict__ q,
                              float* __restrict__ k,
                              float* __restrict__ v) {
    int h = blockIdx.x;
    int s = blockIdx.y;
    int d = threadIdx.x;                 // 0..63
    size_t base_in = (size_t)s * (3 * DIM) + h * HD + d;
    float qv = qkv[base_in];
    float kv = qkv[base_in + DIM];
    float vv = qkv[base_in + 2 * DIM];

    float sq = qv * qv, sk = kv * kv;
#pragma unroll
    for (int o = 16; o > 0; o >>= 1) {
        sq += __shfl_xor_sync(0xffffffffu, sq, o);
        sk += __shfl_xor_sync(0xffffffffu, sk, o);
    }
    __shared__ float pq[2], pk[2];
    __shared__ float sqm[64], skm[64];
    int w = d >> 5;
    if ((d & 31) == 0) { pq[w] = sq; pk[w] = sk; }
    __syncthreads();
    float nq = sqrtf(pq[0] + pq[1]);
    float nk = sqrtf(pk[0] + pk[1]);
    float qn = qv / fmaxf(nq, EPS);
    float kn = kv / fmaxf(nk, EPS);
    sqm[d] = qn;
    skm[d] = kn;
    __syncthreads();

    int i = d & 31;
    bool lo = d < 32;
    float inv = powf(1.0f / 10000.0f, (float)(2 * i) / 64.0f);
    float f = (float)s * inv;
    float c = cosf(f), sn = sinf(f);
    float q1 = sqm[i], q2 = sqm[i + 32];
    float k1 = skm[i], k2 = skm[i + 32];
    float oq = lo ? (q1 * c + q2 * sn) : (-q1 * sn + q2 * c);
    float ok = lo ? (k1 * c + k2 * sn) : (-k1 * sn + k2 * c);

    size_t base_out = ((size_t)h * SEQ + s) * HD + d;
    q[base_out] = oq;
    k[base_out] = ok;
    v[base_out] = vv;
}

// ---------------- causal attention: one warp per query row ----------------
__global__ void attn_kernel(const float* __restrict__ Q,
                            const float* __restrict__ Kt,
                            const float* __restrict__ Vt,
                            float* __restrict__ out) {
    const int QPB = 8;
    int h = blockIdx.x / (SEQ / QPB);
    int qb = blockIdx.x % (SEQ / QPB);
    int tid = threadIdx.x;
    int w = tid >> 5, lane = tid & 31;
    int qi = qb * QPB + w;

    const float* qrow = Q + ((size_t)h * SEQ + qi) * HD;
    float q[HD];
#pragma unroll
    for (int d = 0; d < HD; d++) q[d] = qrow[d];

    __shared__ float Ks[32][HD + 1];
    __shared__ float Vs[32][HD + 1];

    float m = -1e30f, l = 0.f, acc0 = 0.f, acc1 = 0.f;
    int d0 = lane, d1 = lane + 32;
    int qmax = qb * QPB + (QPB - 1);
    int ntiles = qmax / 32 + 1;
    const float scale = 0.125f;

    for (int kb = 0; kb < ntiles; kb++) {
        const float* kbase = Kt + ((size_t)h * SEQ + kb * 32) * HD;
        const float* vbase = Vt + ((size_t)h * SEQ + kb * 32) * HD;
        for (int idx = tid; idx < 32 * HD; idx += 256) {
            int j = idx >> 6, d = idx & 63;
            Ks[j][d] = kbase[idx];
            Vs[j][d] = vbase[idx];
        }
        __syncthreads();
        if (kb * 32 <= qi) {
            int key = kb * 32 + lane;
            float s;
            if (key <= qi) {
                s = 0.f;
#pragma unroll
                for (int d = 0; d < HD; d++) s += q[d] * Ks[lane][d];
                s *= scale;
            } else {
                s = -1e30f;
            }
            float tm = s;
#pragma unroll
            for (int o = 16; o > 0; o >>= 1)
                tm = fmaxf(tm, __shfl_xor_sync(0xffffffffu, tm, o));
            float mnew = fmaxf(m, tm);
            float corr = expf(m - mnew);
            float p = expf(s - mnew);
            float psum = p;
#pragma unroll
            for (int o = 16; o > 0; o >>= 1)
                psum += __shfl_xor_sync(0xffffffffu, psum, o);
            l = l * corr + psum;
            acc0 *= corr;
            acc1 *= corr;
#pragma unroll
            for (int jj = 0; jj < 32; jj++) {
                float pj = __shfl_sync(0xffffffffu, p, jj);
                acc0 += pj * Vs[jj][d0];
                acc1 += pj * Vs[jj][d1];
            }
            m = mnew;
        }
        __syncthreads();
    }
    float inv_l = 1.f / l;
    size_t ob = (size_t)qi * DIM + h * HD;
    out[ob + d0] = acc0 * inv_l;
    out[ob + d1] = acc1 * inv_l;
}

// ---------------- MoE routing: gates + histogram + scan + scatter ------------
__global__ void zero_cnt_kernel() {
    if (threadIdx.x < NEXP) g_cnt[threadIdx.x] = 0;
}

__global__ void gates_count_kernel(const float* __restrict__ logits,
                                   const int* __restrict__ indices,
                                   const float* __restrict__ values) {
    int i = blockIdx.x * blockDim.x + threadIdx.x;
    if (i < NSLOT) {
        int t = i / TOPK;
        int e = indices[i];
        float v = values[i] + logits[t * NEXP + e];
        g_gates[i] = RSF / (1.f + expf(-v));
        atomicAdd(&g_cnt[e], 1);
    }
}

__global__ void scan_kernel() {
    int tid = threadIdx.x;   // 32
    int v = g_cnt[tid];
    int s = v;
#pragma unroll
    for (int o = 1; o < 32; o <<= 1) {
        int n = __shfl_up_sync(0xffffffffu, s, o);
        if (tid >= o) s += n;
    }
    int excl = s - v;
    g_off[tid] = excl;
    g_cur[tid] = excl;
}

__global__ void scatter_kernel(const int* __restrict__ indices) {
    int i = blockIdx.x * blockDim.x + threadIdx.x;
    if (i < NSLOT) {
        int t = i / TOPK;
        int e = indices[i];
        int s = atomicAdd(&g_cur[e], 1);
        g_perm[s] = t;
        g_gatep[s] = g_gates[i];
        g_slot_of[i] = s;
    }
}

// ---------------- MoE grouped GEMM: gather(X) @ W{0,1}[e], N=ED=128 ----------
// mode 0: Out[s,:] = X[tok,:] @ W0[e]      (raw G)
// mode 1: Out[s,:] = silu(G[s,:]) * (X[tok,:] @ W1[e]) * gate[s]
__global__ __launch_bounds__(256) void moe_gemm_kernel(
    const float* __restrict__ X,
    const float* __restrict__ experts,
    int mode) {
    int e = blockIdx.y;
    int c = g_cnt[e];
    int base = g_off[e];
    const float* W = experts + (mode ? (size_t)NEXP * DIM * ED : 0) +
                     (size_t)e * DIM * ED;
    const float* Gp = g_Gbuf;
    float* Out = mode ? g_Hbuf : g_Gbuf;

    __shared__ float As[GBK][GBM];
    __shared__ float Bs[GBK][ED];
    __shared__ int toks[GBM];

    int tid = threadIdx.x;
    int arow = tid >> 1, acol = (tid & 1) << 2;
    int brow = tid >> 5, bcol = (tid & 31) << 2;
    int tx = tid & 15, ty = tid >> 4;

    for (int mt = blockIdx.x; mt * GBM < c; mt += gridDim.x) {
        int m0 = mt * GBM;
        __syncthreads();
        if (tid < GBM) {
            int r = m0 + tid;
            toks[tid] = g_perm[base + ((r < c) ? r : 0)];
        }
        __syncthreads();

        const float* Abase = X + (size_t)toks[arow] * DIM + acol;
        float acc[8][8] = {};
        float4 av = *(const float4*)Abase;
        float4 bv = *(const float4*)(W + (size_t)brow * ED + bcol);

        for (int k0 = 0; k0 < DIM; k0 += GBK) {
            As[acol + 0][arow] = av.x;
            As[acol + 1][arow] = av.y;
            As[acol + 2][arow] = av.z;
            As[acol + 3][arow] = av.w;
            *(float4*)&Bs[brow][bcol] = bv;
            __syncthreads();
            if (k0 + GBK < DIM) {
                av = *(const float4*)(Abase + k0 + GBK);
                bv = *(const float4*)(W + (size_t)(k0 + GBK + brow) * ED + bcol);
            }
#pragma unroll
            for (int kk = 0; kk < GBK; kk++) {
                float a[8], b[8];
                *(float4*)(a)     = *(float4*)&As[kk][ty * 8];
                *(float4*)(a + 4) = *(float4*)&As[kk][ty * 8 + 4];
                *(float4*)(b)     = *(float4*)&Bs[kk][tx * 8];
                *(float4*)(b + 4) = *(float4*)&Bs[kk][tx * 8 + 4];
#pragma unroll
                for (int i = 0; i < 8; i++)
#pragma unroll
                    for (int j = 0; j < 8; j++) acc[i][j] += a[i] * b[j];
            }
            __syncthreads();
        }
#pragma unroll
        for (int i = 0; i < 8; i++) {
            int r = m0 + ty * 8 + i;
            if (r < c) {
                size_t s = (size_t)base + r;
                float* orow = Out + s * ED + tx * 8;
                if (mode == 0) {
                    float4 v0 = make_float4(acc[i][0], acc[i][1], acc[i][2], acc[i][3]);
                    float4 v1 = make_float4(acc[i][4], acc[i][5], acc[i][6], acc[i][7]);
                    *(float4*)orow = v0;
                    *(float4*)(orow + 4) = v1;
                } else {
                    float gate = g_gatep[s];
                    const float* grow = Gp + s * ED + tx * 8;
                    float o[8];
#pragma unroll
                    for (int j = 0; j < 8; j++) {
                        float g = grow[j];
                        float sg = g / (1.f + expf(-g));
                        o[j] = sg * acc[i][j] * gate;
                    }
                    *(float4*)orow = *(float4*)o;
                    *(float4*)(orow + 4) = *(float4*)(o + 4);
                }
            }
        }
    }
}

// ---------------- MoE down: slotbuf[s,:1024] = H[s,:128] @ W2[e]^T ----------
__global__ __launch_bounds__(256) void moe_down_kernel(
    const float* __restrict__ experts) {
    int e = blockIdx.z;
    int c = g_cnt[e];
    int base = g_off[e];
    int n0 = blockIdx.x * GBN;
    const float* W2 = experts + 2 * (size_t)NEXP * DIM * ED + (size_t)e * DIM * ED;

    __shared__ float As[GBK][GBM];
    __shared__ float Bs[GBK][GBN];

    int tid = threadIdx.x;
    int arow = tid >> 1, acol = (tid & 1) << 2;
    int bn = tid >> 1, bj = (tid & 1) << 2;   // B transpose load: n=tid/2, 4 k-vals
    int tx = tid & 15, ty = tid >> 4;

    for (int mt = blockIdx.y; mt * GBM < c; mt += gridDim.y) {
        int m0 = mt * GBM;
        int ar = m0 + arow;
        if (ar >= c) ar = c - 1;
        const float* Abase = g_Hbuf + ((size_t)base + ar) * ED + acol;

        float acc[8][8] = {};
        float4 av = *(const float4*)Abase;
        float4 wv = *(const float4*)(W2 + (size_t)(n0 + bn) * ED + bj);

        for (int k0 = 0; k0 < ED; k0 += GBK) {
            As[acol + 0][arow] = av.x;
            As[acol + 1][arow] = av.y;
            As[acol + 2][arow] = av.z;
            As[acol + 3][arow] = av.w;
            Bs[bj + 0][bn] = wv.x;
            Bs[bj + 1][bn] = wv.y;
            Bs[bj + 2][bn] = wv.z;
            Bs[bj + 3][bn] = wv.w;
            __syncthreads();
            if (k0 + GBK < ED) {
                av = *(const float4*)(Abase + k0 + GBK);
                wv = *(const float4*)(W2 + (size_t)(n0 + bn) * ED + k0 + GBK + bj);
            }
#pragma unroll
            for (int kk = 0; kk < GBK; kk++) {
                float a[8], b[8];
                *(float4*)(a)     = *(float4*)&As[kk][ty * 8];
                *(float4*)(a + 4) = *(float4*)&As[kk][ty * 8 + 4];
                *(float4*)(b)     = *(float4*)&Bs[kk][tx * 8];
                *(float4*)(b + 4) = *(float4*)&Bs[kk][tx * 8 + 4];
#pragma unroll
                for (int i = 0; i < 8; i++)
#pragma unroll
                    for (int j = 0; j < 8; j++) acc[i][j] += a[i] * b[j];
            }
            __syncthreads();
        }
#pragma unroll
        for (int i = 0; i < 8; i++) {
            int r = m0 + ty * 8 + i;
            if (r < c) {
                float* orow = g_slotbuf + ((size_t)base + r) * DIM + n0 + tx * 8;
                float4 v0 = make_float4(acc[i][0], acc[i][1], acc[i][2], acc[i][3]);
                float4 v1 = make_float4(acc[i][4], acc[i][5], acc[i][6], acc[i][7]);
                *(float4*)orow = v0;
                *(float4*)(orow + 4) = v1;
            }
        }
        __syncthreads();
    }
}

// ---------------- combine: y = ffninput + sum_k slotbuf[slot_of[t,k]] --------
__global__ void combine_kernel(const float* __restrict__ ffninput,
                               float* __restrict__ y) {
    int t = blockIdx.x;
    int tid = threadIdx.x;   // 256
    int slots[TOPK];
#pragma unroll
    for (int k = 0; k < TOPK; k++) slots[k] = g_slot_of[t * TOPK + k];
#pragma unroll
    for (int i = 0; i < 4; i++) {
        int d = tid + i * 256;
        float s = ffninput[(size_t)t * DIM + d];
#pragma unroll
        for (int k = 0; k < TOPK; k++)
            s += g_slotbuf[(size_t)slots[k] * DIM + d];
        y[(size_t)t * DIM + d] = s;
    }
}

// ---------------- swiglu on shared-expert up projection ----------------
__global__ void swiglu_kernel(const float* __restrict__ up, float* __restrict__ act) {
    int i = blockIdx.x * blockDim.x + threadIdx.x;
    if (i < SEQ * DSH) {
        int t = i / DSH, j = i % DSH;
        float x1 = up[(size_t)t * (2 * DSH) + j];
        float x2 = up[(size_t)t * (2 * DSH) + DSH + j];
        act[i] = (x1 / (1.f + expf(-x1))) * x2;
    }
}

// ---------------- launch ----------------
extern "C" void kernel_launch(void* const* d_in, const int* in_sizes, int n_in,
                              void* d_out, int out_size) {
    const float* x_input     = (const float*)d_in[0];
    const int*   indices     = (const int*)d_in[1];
    const float* values      = (const float*)d_in[2];
    const float* w_attn      = (const float*)d_in[3];
    const float* w_attn_o    = (const float*)d_in[4];
    const float* attn_norm_w = (const float*)d_in[5];
    const float* ffn_norm_w  = (const float*)d_in[6];
    const float* ffn_experts = (const float*)d_in[7];
    const float* keys_w      = (const float*)d_in[8];
    const float* w_up        = (const float*)d_in[9];
    const float* w_down      = (const float*)d_in[10];
    float* out = (float*)d_out;

    float *p_xnorm, *p_qkv, *p_q, *p_k, *p_v, *p_attn, *p_ffninput, *p_xffn;
    float *p_logits, *p_y, *p_upb, *p_act;
    cudaGetSymbolAddress((void**)&p_xnorm, g_xnorm);
    cudaGetSymbolAddress((void**)&p_qkv, g_qkv);
    cudaGetSymbolAddress((void**)&p_q, g_q);
    cudaGetSymbolAddress((void**)&p_k, g_k);
    cudaGetSymbolAddress((void**)&p_v, g_v);
    cudaGetSymbolAddress((void**)&p_attn, g_attn);
    cudaGetSymbolAddress((void**)&p_ffninput, g_ffninput);
    cudaGetSymbolAddress((void**)&p_xffn, g_xffn);
    cudaGetSymbolAddress((void**)&p_logits, g_logits);
    cudaGetSymbolAddress((void**)&p_y, g_y);
    cudaGetSymbolAddress((void**)&p_upb, g_up);
    cudaGetSymbolAddress((void**)&p_act, g_act);

    dim3 b256(256);

    // 1. attn rmsnorm
    rmsnorm_kernel<<<SEQ, b256>>>(x_input, attn_norm_w, p_xnorm);
    // 2. qkv projection
    {
        dim3 grid((3 * DIM) / GBN, SEQ / GBM);
        sgemm128_kernel<<<grid, b256>>>(p_xnorm, w_attn, p_qkv, nullptr, 3 * DIM, DIM);
    }
    // 3. l2norm + rope
    {
        dim3 grid(NH, SEQ);
        qkprep_kernel<<<grid, 64>>>(p_qkv, p_q, p_k, p_v);
    }
    // 4. causal attention
    attn_kernel<<<NH * (SEQ / 8), b256>>>(p_q, p_k, p_v, p_attn);
    // 5. output projection + residual
    {
        dim3 grid(DIM / GBN, SEQ / GBM);
        sgemm128_kernel<<<grid, b256>>>(p_attn, w_attn_o, p_ffninput, x_input, DIM, DIM);
    }
    // 6. ffn rmsnorm
    rmsnorm_kernel<<<SEQ, b256>>>(p_ffninput, ffn_norm_w, p_xffn);
    // 7. router logits (small guarded gemm)
    {
        dim3 grid(1, SEQ / BM);
        sgemm_kernel<<<grid, b256>>>(p_xffn, keys_w, p_logits, nullptr, SEQ, NEXP, DIM);
    }
    // 8. routing: gates + count + scan + scatter
    zero_cnt_kernel<<<1, 32>>>();
    gates_count_kernel<<<(NSLOT + 255) / 256, b256>>>(p_logits, indices, values);
    scan_kernel<<<1, 32>>>();
    scatter_kernel<<<(NSLOT + 255) / 256, b256>>>(indices);
    // 9. grouped expert GEMMs
    {
        dim3 grid(16, NEXP);  // m-tiles (grid-strided), experts
        moe_gemm_kernel<<<grid, b256>>>(p_xffn, ffn_experts, 0);
        moe_gemm_kernel<<<grid, b256>>>(p_xffn, ffn_experts, 1);
        dim3 gridd(DIM / GBN, 8, NEXP);  // n-tiles, m-tiles (grid-strided), experts
        moe_down_kernel<<<gridd, b256>>>(ffn_experts);
    }
    // 10. combine slots + ffn residual
    combine_kernel<<<SEQ, b256>>>(p_ffninput, p_y);
    // 11. shared expert up
    {
        dim3 grid((2 * DSH) / GBN, SEQ / GBM);
        sgemm128_kernel<<<grid, b256>>>(p_xffn, w_up, p_upb, nullptr, 2 * DSH, DIM);
    }
    // 12. swiglu
    swiglu_kernel<<<(SEQ * DSH + 255) / 256, b256>>>(p_upb, p_act);
    // 13. shared expert down + (moe + residual) epilogue -> final output
    {
        dim3 grid(DIM / GBN, SEQ / GBM);
        sgemm128_kernel<<<grid, b256>>>(p_act, w_down, out, p_y, DIM, DSH);
    }
}

// round 9
// speedup vs baseline: 4.8292x; 1.4453x over previous
#include <cuda_runtime.h>
#include <math.h>
#include <stdint.h>

// ---------------- problem constants ----------------
#define SEQ   2048
#define DIM   1024
#define NH    16
#define HD    64
#define NEXP  32
#define ED    128
#define TOPK  8
#define DSH   2048
#define EPS   1e-6f
#define RSF   2.5f

#define NSLOT (SEQ * TOPK)   // 16384 assignments

// ---------------- scratch (device globals; no allocation allowed) ----------------
__device__ float g_xnorm[SEQ * DIM];
__device__ float g_qkv[SEQ * 3 * DIM];
__device__ float g_q[NH * SEQ * HD];
__device__ float g_k[NH * SEQ * HD];
__device__ float g_v[NH * SEQ * HD];
__device__ float g_attn[SEQ * DIM];
__device__ float g_ffninput[SEQ * DIM];
__device__ float g_xffn[SEQ * DIM];
__device__ float g_logits[SEQ * NEXP];
__device__ float g_gates[NSLOT];
__device__ float g_y[SEQ * DIM];
__device__ float g_up[SEQ * 2 * DSH];
__device__ float g_act[SEQ * DSH];

// MoE grouped-GEMM scratch
__device__ int   g_cnt[NEXP];
__device__ int   g_off[NEXP];
__device__ int   g_cur[NEXP];
__device__ int   g_perm[NSLOT];      // slot -> token
__device__ int   g_slot_of[NSLOT];   // (t,k) -> slot
__device__ float g_gatep[NSLOT];     // slot -> gate
__device__ float g_Gbuf[NSLOT * ED];
__device__ float g_Hbuf[NSLOT * ED];
__device__ float g_slotbuf[NSLOT * DIM];

// ---------------- tf32 helpers ----------------
__device__ __forceinline__ float tf32r(float x) {
    uint32_t u;
    asm("cvt.rna.tf32.f32 %0, %1;" : "=r"(u) : "f"(x));
    return __uint_as_float(u);
}
__device__ __forceinline__ float4 tf32r4(float4 v) {
    v.x = tf32r(v.x); v.y = tf32r(v.y); v.z = tf32r(v.z); v.w = tf32r(v.w);
    return v;
}

#define MMA_TF32(c, a, b)                                                    \
    asm volatile(                                                            \
        "mma.sync.aligned.m16n8k8.row.col.f32.tf32.tf32.f32 "                \
        "{%0,%1,%2,%3}, {%4,%5,%6,%7}, {%8,%9}, {%0,%1,%2,%3};"              \
        : "+f"((c)[0]), "+f"((c)[1]), "+f"((c)[2]), "+f"((c)[3])             \
        : "r"((a)[0]), "r"((a)[1]), "r"((a)[2]), "r"((a)[3]),                \
          "r"((b)[0]), "r"((b)[1]))

// ---------------- rmsnorm: one block per row ----------------
__global__ void rmsnorm_kernel(const float* __restrict__ x,
                               const float* __restrict__ w,
                               float* __restrict__ out) {
    int t = blockIdx.x;
    int tid = threadIdx.x;               // 256
    const float* xr = x + (size_t)t * DIM;
    float vals[4];
    float s = 0.f;
#pragma unroll
    for (int i = 0; i < 4; i++) {
        float v = xr[tid + i * 256];
        vals[i] = v;
        s += v * v;
    }
#pragma unroll
    for (int o = 16; o > 0; o >>= 1) s += __shfl_xor_sync(0xffffffffu, s, o);
    __shared__ float red[8];
    int warp = tid >> 5;
    if ((tid & 31) == 0) red[warp] = s;
    __syncthreads();
    if (tid == 0) {
        float tot = 0.f;
#pragma unroll
        for (int i = 0; i < 8; i++) tot += red[i];
        red[0] = 1.f / sqrtf(tot / (float)DIM + EPS);
    }
    __syncthreads();
    float sc = red[0];
    float* orow = out + (size_t)t * DIM;
#pragma unroll
    for (int i = 0; i < 4; i++) {
        int c = tid + i * 256;
        orow[c] = vals[i] * sc * w[c];
    }
}

// ---------------- small guarded fp32 GEMM (router only) ----------------
#define BM 64
#define BN 64
#define BK 16
__global__ void sgemm_kernel(const float* __restrict__ A,
                             const float* __restrict__ B,
                             float* __restrict__ C,
                             const float* __restrict__ res,
                             int M, int N, int Kd) {
    __shared__ float As[BK][BM];
    __shared__ float Bs[BK][BN];
    int tid = threadIdx.x;
    int bx = blockIdx.x, by = blockIdx.y;
    int tx = tid & 15, ty = tid >> 4;
    int row0 = by * BM + ty * 4;
    int col0 = bx * BN + tx * 4;
    float acc[4][4] = {};
    int ar = tid >> 2, ac = (tid & 3) * 4;
    int br = tid >> 4, bc = (tid & 15) * 4;

    for (int k0 = 0; k0 < Kd; k0 += BK) {
        float4 av = *(const float4*)&A[(size_t)(by * BM + ar) * Kd + k0 + ac];
        As[ac + 0][ar] = av.x;
        As[ac + 1][ar] = av.y;
        As[ac + 2][ar] = av.z;
        As[ac + 3][ar] = av.w;
        float4 bv = make_float4(0.f, 0.f, 0.f, 0.f);
        int bcol = bx * BN + bc;
        if (bcol < N) bv = *(const float4*)&B[(size_t)(k0 + br) * N + bcol];
        *(float4*)&Bs[br][bc] = bv;
        __syncthreads();
#pragma unroll
        for (int kk = 0; kk < BK; kk++) {
            float4 a4 = *(float4*)&As[kk][ty * 4];
            float4 b4 = *(float4*)&Bs[kk][tx * 4];
            float a[4] = {a4.x, a4.y, a4.z, a4.w};
            float b[4] = {b4.x, b4.y, b4.z, b4.w};
#pragma unroll
            for (int i = 0; i < 4; i++)
#pragma unroll
                for (int j = 0; j < 4; j++) acc[i][j] += a[i] * b[j];
        }
        __syncthreads();
    }
#pragma unroll
    for (int i = 0; i < 4; i++) {
        int r = row0 + i;
#pragma unroll
        for (int j = 0; j < 4; j++) {
            int c = col0 + j;
            if (c < N) {
                float v = acc[i][j];
                if (res) v += res[(size_t)r * N + c];
                C[(size_t)r * N + c] = v;
            }
        }
    }
}

// ============== tf32 tensor-core GEMM: 128x128x32, 8 warps, 64x32 per warp ====
// C[M,N] = A[M,K] @ B[K,N]   (row-major A, row-major B)
// requires M%128==0, N%128==0, K%32==0
__global__ __launch_bounds__(256) void tc_gemm_kernel(
    const float* __restrict__ A, const float* __restrict__ B,
    float* __restrict__ C, const float* __restrict__ res, int N, int K) {
    __shared__ float As[128][36];   // pad 4: frag bank = 4r+c (conflict-free)
    __shared__ float Bs[32][136];   // pad 8: frag bank = 8k+n (conflict-free)
    int tid = threadIdx.x;
    int lane = tid & 31, wid = tid >> 5;
    int wm = (wid >> 2) * 64;
    int wn = (wid & 3) * 32;
    int bx = blockIdx.x, by = blockIdx.y;

    int arow = tid >> 1, acoff = (tid & 1) * 16;
    int brow = tid >> 3, bcoff = (tid & 7) * 16;

    const float* Ag = A + (size_t)(by * 128 + arow) * K + acoff;
    const float* Bg = B + (size_t)brow * N + bx * 128 + bcoff;

    float4 aprf[4], bprf[4];
#pragma unroll
    for (int i = 0; i < 4; i++) {
        aprf[i] = *(const float4*)(Ag + 4 * i);
        bprf[i] = *(const float4*)(Bg + 4 * i);
    }

    float acc[4][4][4];
#pragma unroll
    for (int a = 0; a < 4; a++)
#pragma unroll
        for (int b = 0; b < 4; b++)
#pragma unroll
            for (int c = 0; c < 4; c++) acc[a][b][c] = 0.f;

    for (int k0 = 0; k0 < K; k0 += 32) {
#pragma unroll
        for (int i = 0; i < 4; i++) {
            *(float4*)&As[arow][acoff + 4 * i] = tf32r4(aprf[i]);
            *(float4*)&Bs[brow][bcoff + 4 * i] = tf32r4(bprf[i]);
        }
        __syncthreads();
        if (k0 + 32 < K) {
#pragma unroll
            for (int i = 0; i < 4; i++) {
                aprf[i] = *(const float4*)(Ag + k0 + 32 + 4 * i);
                bprf[i] = *(const float4*)(Bg + (size_t)(k0 + 32) * N + 4 * i);
            }
        }
#pragma unroll
        for (int kk = 0; kk < 4; kk++) {
            int kb = kk * 8;
            uint32_t af[4][4], bf[4][2];
#pragma unroll
            for (int mt = 0; mt < 4; mt++) {
                int r = wm + mt * 16 + (lane >> 2);
                int c = kb + (lane & 3);
                af[mt][0] = __float_as_uint(As[r][c]);
                af[mt][1] = __float_as_uint(As[r + 8][c]);
                af[mt][2] = __float_as_uint(As[r][c + 4]);
                af[mt][3] = __float_as_uint(As[r + 8][c + 4]);
            }
#pragma unroll
            for (int nt = 0; nt < 4; nt++) {
                int cc = wn + nt * 8 + (lane >> 2);
                bf[nt][0] = __float_as_uint(Bs[kb + (lane & 3)][cc]);
                bf[nt][1] = __float_as_uint(Bs[kb + 4 + (lane & 3)][cc]);
            }
#pragma unroll
            for (int mt = 0; mt < 4; mt++)
#pragma unroll
                for (int nt = 0; nt < 4; nt++) MMA_TF32(acc[mt][nt], af[mt], bf[nt]);
        }
        __syncthreads();
    }
    // epilogue
#pragma unroll
    for (int mt = 0; mt < 4; mt++) {
#pragma unroll
        for (int nt = 0; nt < 4; nt++) {
            int r0 = by * 128 + wm + mt * 16 + (lane >> 2);
            int c0 = bx * 128 + wn + nt * 8 + (lane & 3) * 2;
            float v0 = acc[mt][nt][0], v1 = acc[mt][nt][1];
            float v2 = acc[mt][nt][2], v3 = acc[mt][nt][3];
            if (res) {
                v0 += res[(size_t)r0 * N + c0];
                v1 += res[(size_t)r0 * N + c0 + 1];
                v2 += res[(size_t)(r0 + 8) * N + c0];
                v3 += res[(size_t)(r0 + 8) * N + c0 + 1];
            }
            C[(size_t)r0 * N + c0] = v0;
            C[(size_t)r0 * N + c0 + 1] = v1;
            C[(size_t)(r0 + 8) * N + c0] = v2;
            C[(size_t)(r0 + 8) * N + c0 + 1] = v3;
        }
    }
}

// ---------------- q/k l2norm + rope, v passthrough ----------------
__global__ void qkprep_kernel(const float* __restrict__ qkv,
                              float* __restrict__ q,
                              float* __restrict__ k,
                              float* __restrict__ v) {
    int h = blockIdx.x;
    int s = blockIdx.y;
    int d = threadIdx.x;                 // 0..63
    size_t base_in = (size_t)s * (3 * DIM) + h * HD + d;
    float qv = qkv[base_in];
    float kv = qkv[base_in + DIM];
    float vv = qkv[base_in + 2 * DIM];

    float sq = qv * qv, sk = kv * kv;
#pragma unroll
    for (int o = 16; o > 0; o >>= 1) {
        sq += __shfl_xor_sync(0xffffffffu, sq, o);
        sk += __shfl_xor_sync(0xffffffffu, sk, o);
    }
    __shared__ float pq[2], pk[2];
    __shared__ float sqm[64], skm[64];
    int w = d >> 5;
    if ((d & 31) == 0) { pq[w] = sq; pk[w] = sk; }
    __syncthreads();
    float nq = sqrtf(pq[0] + pq[1]);
    float nk = sqrtf(pk[0] + pk[1]);
    float qn = qv / fmaxf(nq, EPS);
    float kn = kv / fmaxf(nk, EPS);
    sqm[d] = qn;
    skm[d] = kn;
    __syncthreads();

    int i = d & 31;
    bool lo = d < 32;
    float inv = powf(1.0f / 10000.0f, (float)(2 * i) / 64.0f);
    float f = (float)s * inv;
    float c = cosf(f), sn = sinf(f);
    float q1 = sqm[i], q2 = sqm[i + 32];
    float k1 = skm[i], k2 = skm[i + 32];
    float oq = lo ? (q1 * c + q2 * sn) : (-q1 * sn + q2 * c);
    float ok = lo ? (k1 * c + k2 * sn) : (-k1 * sn + k2 * c);

    size_t base_out = ((size_t)h * SEQ + s) * HD + d;
    q[base_out] = oq;
    k[base_out] = ok;
    v[base_out] = vv;
}

// ---------------- causal attention: one warp per query row ----------------
__global__ void attn_kernel(const float* __restrict__ Q,
                            const float* __restrict__ Kt,
                            const float* __restrict__ Vt,
                            float* __restrict__ out) {
    const int QPB = 8;
    int h = blockIdx.x / (SEQ / QPB);
    int qb = blockIdx.x % (SEQ / QPB);
    int tid = threadIdx.x;
    int w = tid >> 5, lane = tid & 31;
    int qi = qb * QPB + w;

    const float* qrow = Q + ((size_t)h * SEQ + qi) * HD;
    float q[HD];
#pragma unroll
    for (int d = 0; d < HD; d++) q[d] = qrow[d];

    __shared__ float Ks[32][HD + 1];
    __shared__ float Vs[32][HD + 1];

    float m = -1e30f, l = 0.f, acc0 = 0.f, acc1 = 0.f;
    int d0 = lane, d1 = lane + 32;
    int qmax = qb * QPB + (QPB - 1);
    int ntiles = qmax / 32 + 1;
    const float scale = 0.125f;

    for (int kb = 0; kb < ntiles; kb++) {
        const float* kbase = Kt + ((size_t)h * SEQ + kb * 32) * HD;
        const float* vbase = Vt + ((size_t)h * SEQ + kb * 32) * HD;
        for (int idx = tid; idx < 32 * HD; idx += 256) {
            int j = idx >> 6, d = idx & 63;
            Ks[j][d] = kbase[idx];
            Vs[j][d] = vbase[idx];
        }
        __syncthreads();
        if (kb * 32 <= qi) {
            int key = kb * 32 + lane;
            float s;
            if (key <= qi) {
                s = 0.f;
#pragma unroll
                for (int d = 0; d < HD; d++) s += q[d] * Ks[lane][d];
                s *= scale;
            } else {
                s = -1e30f;
            }
            float tm = s;
#pragma unroll
            for (int o = 16; o > 0; o >>= 1)
                tm = fmaxf(tm, __shfl_xor_sync(0xffffffffu, tm, o));
            float mnew = fmaxf(m, tm);
            float corr = expf(m - mnew);
            float p = expf(s - mnew);
            float psum = p;
#pragma unroll
            for (int o = 16; o > 0; o >>= 1)
                psum += __shfl_xor_sync(0xffffffffu, psum, o);
            l = l * corr + psum;
            acc0 *= corr;
            acc1 *= corr;
#pragma unroll
            for (int jj = 0; jj < 32; jj++) {
                float pj = __shfl_sync(0xffffffffu, p, jj);
                acc0 += pj * Vs[jj][d0];
                acc1 += pj * Vs[jj][d1];
            }
            m = mnew;
        }
        __syncthreads();
    }
    float inv_l = 1.f / l;
    size_t ob = (size_t)qi * DIM + h * HD;
    out[ob + d0] = acc0 * inv_l;
    out[ob + d1] = acc1 * inv_l;
}

// ---------------- MoE routing: gates + histogram + scan + scatter ------------
__global__ void zero_cnt_kernel() {
    if (threadIdx.x < NEXP) g_cnt[threadIdx.x] = 0;
}

__global__ void gates_count_kernel(const float* __restrict__ logits,
                                   const int* __restrict__ indices,
                                   const float* __restrict__ values) {
    int i = blockIdx.x * blockDim.x + threadIdx.x;
    if (i < NSLOT) {
        int t = i / TOPK;
        int e = indices[i];
        float v = values[i] + logits[t * NEXP + e];
        g_gates[i] = RSF / (1.f + expf(-v));
        atomicAdd(&g_cnt[e], 1);
    }
}

__global__ void scan_kernel() {
    int tid = threadIdx.x;   // 32
    int v = g_cnt[tid];
    int s = v;
#pragma unroll
    for (int o = 1; o < 32; o <<= 1) {
        int n = __shfl_up_sync(0xffffffffu, s, o);
        if (tid >= o) s += n;
    }
    int excl = s - v;
    g_off[tid] = excl;
    g_cur[tid] = excl;
}

__global__ void scatter_kernel(const int* __restrict__ indices) {
    int i = blockIdx.x * blockDim.x + threadIdx.x;
    if (i < NSLOT) {
        int t = i / TOPK;
        int e = indices[i];
        int s = atomicAdd(&g_cur[e], 1);
        g_perm[s] = t;
        g_gatep[s] = g_gates[i];
        g_slot_of[i] = s;
    }
}

// ====== tf32 MoE up/gate GEMM: gather(X)[c x DIM] @ W[DIM x ED], ED=128 ======
// mode 0: Gbuf[s,:] = X[tok,:] @ W0[e]
// mode 1: Hbuf[s,:] = silu(Gbuf[s,:]) * (X[tok,:] @ W1[e]) * gate[s]
__global__ __launch_bounds__(256) void tc_moe_gemm_kernel(
    const float* __restrict__ X, const float* __restrict__ experts, int mode) {
    int e = blockIdx.y;
    int c = g_cnt[e];
    int base = g_off[e];
    const size_t MAT = (size_t)NEXP * DIM * ED;
    const float* W = experts + (mode ? MAT : 0) + (size_t)e * DIM * ED;

    __shared__ float As[128][36];
    __shared__ float Bs[32][136];
    __shared__ int toks[128];

    int tid = threadIdx.x;
    int lane = tid & 31, wid = tid >> 5;
    int wm = (wid >> 2) * 64;
    int wn = (wid & 3) * 32;
    int arow = tid >> 1, acoff = (tid & 1) * 16;
    int brow = tid >> 3, bcoff = (tid & 7) * 16;

    for (int mt0 = blockIdx.x; mt0 * 128 < c; mt0 += gridDim.x) {
        int m0 = mt0 * 128;
        __syncthreads();
        if (tid < 128) {
            int r = m0 + tid;
            toks[tid] = g_perm[base + ((r < c) ? r : c - 1)];
        }
        __syncthreads();

        const float* Ag = X + (size_t)toks[arow] * DIM + acoff;
        const float* Bg = W + (size_t)brow * ED + bcoff;

        float4 aprf[4], bprf[4];
#pragma unroll
        for (int i = 0; i < 4; i++) {
            aprf[i] = *(const float4*)(Ag + 4 * i);
            bprf[i] = *(const float4*)(Bg + 4 * i);
        }
        float acc[4][4][4];
#pragma unroll
        for (int a = 0; a < 4; a++)
#pragma unroll
            for (int b = 0; b < 4; b++)
#pragma unroll
                for (int d = 0; d < 4; d++) acc[a][b][d] = 0.f;

        for (int k0 = 0; k0 < DIM; k0 += 32) {
#pragma unroll
            for (int i = 0; i < 4; i++) {
                *(float4*)&As[arow][acoff + 4 * i] = tf32r4(aprf[i]);
                *(float4*)&Bs[brow][bcoff + 4 * i] = tf32r4(bprf[i]);
            }
            __syncthreads();
            if (k0 + 32 < DIM) {
#pragma unroll
                for (int i = 0; i < 4; i++) {
                    aprf[i] = *(const float4*)(Ag + k0 + 32 + 4 * i);
                    bprf[i] = *(const float4*)(Bg + (size_t)(k0 + 32) * ED + 4 * i);
                }
            }
#pragma unroll
            for (int kk = 0; kk < 4; kk++) {
                int kb = kk * 8;
                uint32_t af[4][4], bf[4][2];
#pragma unroll
                for (int mt = 0; mt < 4; mt++) {
                    int r = wm + mt * 16 + (lane >> 2);
                    int cc = kb + (lane & 3);
                    af[mt][0] = __float_as_uint(As[r][cc]);
                    af[mt][1] = __float_as_uint(As[r + 8][cc]);
                    af[mt][2] = __float_as_uint(As[r][cc + 4]);
                    af[mt][3] = __float_as_uint(As[r + 8][cc + 4]);
                }
#pragma unroll
                for (int nt = 0; nt < 4; nt++) {
                    int cc = wn + nt * 8 + (lane >> 2);
                    bf[nt][0] = __float_as_uint(Bs[kb + (lane & 3)][cc]);
                    bf[nt][1] = __float_as_uint(Bs[kb + 4 + (lane & 3)][cc]);
                }
#pragma unroll
                for (int mt = 0; mt < 4; mt++)
#pragma unroll
                    for (int nt = 0; nt < 4; nt++) MMA_TF32(acc[mt][nt], af[mt], bf[nt]);
            }
            __syncthreads();
        }
        // epilogue
#pragma unroll
        for (int mt = 0; mt < 4; mt++) {
#pragma unroll
            for (int nt = 0; nt < 4; nt++) {
#pragma unroll
                for (int half = 0; half < 2; half++) {
                    int r = m0 + wm + mt * 16 + (lane >> 2) + half * 8;
                    if (r < c) {
                        size_t s = (size_t)base + r;
                        int col = wn + nt * 8 + (lane & 3) * 2;
                        float v0 = acc[mt][nt][half * 2];
                        float v1 = acc[mt][nt][half * 2 + 1];
                        if (mode == 0) {
                            g_Gbuf[s * ED + col] = v0;
                            g_Gbuf[s * ED + col + 1] = v1;
                        } else {
                            float gate = g_gatep[s];
                            float g0 = g_Gbuf[s * ED + col];
                            float g1 = g_Gbuf[s * ED + col + 1];
                            g_Hbuf[s * ED + col] =
                                (g0 / (1.f + expf(-g0))) * v0 * gate;
                            g_Hbuf[s * ED + col + 1] =
                                (g1 / (1.f + expf(-g1))) * v1 * gate;
                        }
                    }
                }
            }
        }
    }
}

// ====== tf32 MoE down GEMM: slotbuf[c x DIM] = H[c x ED] @ W2[e]^T ===========
// W2 stored [DIM][ED]; B[k=h][n=d] = W2[d][h] -> transpose at staging
__global__ __launch_bounds__(256) void tc_moe_down_kernel(
    const float* __restrict__ experts) {
    int e = blockIdx.z;
    int c = g_cnt[e];
    int base = g_off[e];
    int n0 = blockIdx.x * 128;
    const float* W2 = experts + 2 * (size_t)NEXP * DIM * ED + (size_t)e * DIM * ED;

    __shared__ float As[128][36];
    __shared__ float Bs[32][136];

    int tid = threadIdx.x;
    int lane = tid & 31, wid = tid >> 5;
    int wm = (wid >> 2) * 64;
    int wn = (wid & 3) * 32;
    int arow = tid >> 1, acoff = (tid & 1) * 16;
    int bd = tid >> 1, bhoff = (tid & 1) * 16;   // transpose staging

    for (int mt0 = blockIdx.y; mt0 * 128 < c; mt0 += gridDim.y) {
        int m0 = mt0 * 128;
        int ar = m0 + arow;
        if (ar >= c) ar = c - 1;
        const float* Ag = g_Hbuf + ((size_t)base + ar) * ED + acoff;
        const float* Bg = W2 + (size_t)(n0 + bd) * ED + bhoff;

        float4 aprf[4], bprf[4];
#pragma unroll
        for (int i = 0; i < 4; i++) {
            aprf[i] = *(const float4*)(Ag + 4 * i);
            bprf[i] = *(const float4*)(Bg + 4 * i);
        }
        float acc[4][4][4];
#pragma unroll
        for (int a = 0; a < 4; a++)
#pragma unroll
            for (int b = 0; b < 4; b++)
#pragma unroll
                for (int d = 0; d < 4; d++) acc[a][b][d] = 0.f;

        for (int k0 = 0; k0 < ED; k0 += 32) {
#pragma unroll
            for (int i = 0; i < 4; i++) {
                *(float4*)&As[arow][acoff + 4 * i] = tf32r4(aprf[i]);
                float4 wv = bprf[i];
                Bs[bhoff + 4 * i + 0][bd] = tf32r(wv.x);
                Bs[bhoff + 4 * i + 1][bd] = tf32r(wv.y);
                Bs[bhoff + 4 * i + 2][bd] = tf32r(wv.z);
                Bs[bhoff + 4 * i + 3][bd] = tf32r(wv.w);
            }
            __syncthreads();
            if (k0 + 32 < ED) {
#pragma unroll
                for (int i = 0; i < 4; i++) {
                    aprf[i] = *(const float4*)(Ag + k0 + 32 + 4 * i);
                    bprf[i] = *(const float4*)(Bg + k0 + 32 + 4 * i);
                }
            }
#pragma unroll
            for (int kk = 0; kk < 4; kk++) {
                int kb = kk * 8;
                uint32_t af[4][4], bf[4][2];
#pragma unroll
                for (int mt = 0; mt < 4; mt++) {
                    int r = wm + mt * 16 + (lane >> 2);
                    int cc = kb + (lane & 3);
                    af[mt][0] = __float_as_uint(As[r][cc]);
                    af[mt][1] = __float_as_uint(As[r + 8][cc]);
                    af[mt][2] = __float_as_uint(As[r][cc + 4]);
                    af[mt][3] = __float_as_uint(As[r + 8][cc + 4]);
                }
#pragma unroll
                for (int nt = 0; nt < 4; nt++) {
                    int cc = wn + nt * 8 + (lane >> 2);
                    bf[nt][0] = __float_as_uint(Bs[kb + (lane & 3)][cc]);
                    bf[nt][1] = __float_as_uint(Bs[kb + 4 + (lane & 3)][cc]);
                }
#pragma unroll
                for (int mt = 0; mt < 4; mt++)
#pragma unroll
                    for (int nt = 0; nt < 4; nt++) MMA_TF32(acc[mt][nt], af[mt], bf[nt]);
            }
            __syncthreads();
        }
#pragma unroll
        for (int mt = 0; mt < 4; mt++) {
#pragma unroll
            for (int nt = 0; nt < 4; nt++) {
#pragma unroll
                for (int half = 0; half < 2; half++) {
                    int r = m0 + wm + mt * 16 + (lane >> 2) + half * 8;
                    if (r < c) {
                        int col = n0 + wn + nt * 8 + (lane & 3) * 2;
                        float* orow = g_slotbuf + ((size_t)base + r) * DIM + col;
                        orow[0] = acc[mt][nt][half * 2];
                        orow[1] = acc[mt][nt][half * 2 + 1];
                    }
                }
            }
        }
        __syncthreads();
    }
}

// ---------------- combine: y = ffninput + sum_k slotbuf[slot_of[t,k]] --------
__global__ void combine_kernel(const float* __restrict__ ffninput,
                               float* __restrict__ y) {
    int t = blockIdx.x;
    int tid = threadIdx.x;   // 256
    int slots[TOPK];
#pragma unroll
    for (int k = 0; k < TOPK; k++) slots[k] = g_slot_of[t * TOPK + k];
#pragma unroll
    for (int i = 0; i < 4; i++) {
        int d = tid + i * 256;
        float s = ffninput[(size_t)t * DIM + d];
#pragma unroll
        for (int k = 0; k < TOPK; k++)
            s += g_slotbuf[(size_t)slots[k] * DIM + d];
        y[(size_t)t * DIM + d] = s;
    }
}

// ---------------- swiglu on shared-expert up projection ----------------
__global__ void swiglu_kernel(const float* __restrict__ up, float* __restrict__ act) {
    int i = blockIdx.x * blockDim.x + threadIdx.x;
    if (i < SEQ * DSH) {
        int t = i / DSH, j = i % DSH;
        float x1 = up[(size_t)t * (2 * DSH) + j];
        float x2 = up[(size_t)t * (2 * DSH) + DSH + j];
        act[i] = (x1 / (1.f + expf(-x1))) * x2;
    }
}

// ---------------- launch ----------------
extern "C" void kernel_launch(void* const* d_in, const int* in_sizes, int n_in,
                              void* d_out, int out_size) {
    const float* x_input     = (const float*)d_in[0];
    const int*   indices     = (const int*)d_in[1];
    const float* values      = (const float*)d_in[2];
    const float* w_attn      = (const float*)d_in[3];
    const float* w_attn_o    = (const float*)d_in[4];
    const float* attn_norm_w = (const float*)d_in[5];
    const float* ffn_norm_w  = (const float*)d_in[6];
    const float* ffn_experts = (const float*)d_in[7];
    const float* keys_w      = (const float*)d_in[8];
    const float* w_up        = (const float*)d_in[9];
    const float* w_down      = (const float*)d_in[10];
    float* out = (float*)d_out;

    float *p_xnorm, *p_qkv, *p_q, *p_k, *p_v, *p_attn, *p_ffninput, *p_xffn;
    float *p_logits, *p_y, *p_upb, *p_act;
    cudaGetSymbolAddress((void**)&p_xnorm, g_xnorm);
    cudaGetSymbolAddress((void**)&p_qkv, g_qkv);
    cudaGetSymbolAddress((void**)&p_q, g_q);
    cudaGetSymbolAddress((void**)&p_k, g_k);
    cudaGetSymbolAddress((void**)&p_v, g_v);
    cudaGetSymbolAddress((void**)&p_attn, g_attn);
    cudaGetSymbolAddress((void**)&p_ffninput, g_ffninput);
    cudaGetSymbolAddress((void**)&p_xffn, g_xffn);
    cudaGetSymbolAddress((void**)&p_logits, g_logits);
    cudaGetSymbolAddress((void**)&p_y, g_y);
    cudaGetSymbolAddress((void**)&p_upb, g_up);
    cudaGetSymbolAddress((void**)&p_act, g_act);

    dim3 b256(256);

    // 1. attn rmsnorm
    rmsnorm_kernel<<<SEQ, b256>>>(x_input, attn_norm_w, p_xnorm);
    // 2. qkv projection (tf32 TC)
    {
        dim3 grid((3 * DIM) / 128, SEQ / 128);
        tc_gemm_kernel<<<grid, b256>>>(p_xnorm, w_attn, p_qkv, nullptr, 3 * DIM, DIM);
    }
    // 3. l2norm + rope
    {
        dim3 grid(NH, SEQ);
        qkprep_kernel<<<grid, 64>>>(p_qkv, p_q, p_k, p_v);
    }
    // 4. causal attention
    attn_kernel<<<NH * (SEQ / 8), b256>>>(p_q, p_k, p_v, p_attn);
    // 5. output projection + residual (tf32 TC)
    {
        dim3 grid(DIM / 128, SEQ / 128);
        tc_gemm_kernel<<<grid, b256>>>(p_attn, w_attn_o, p_ffninput, x_input, DIM, DIM);
    }
    // 6. ffn rmsnorm
    rmsnorm_kernel<<<SEQ, b256>>>(p_ffninput, ffn_norm_w, p_xffn);
    // 7. router logits (fp32, exact)
    {
        dim3 grid(1, SEQ / BM);
        sgemm_kernel<<<grid, b256>>>(p_xffn, keys_w, p_logits, nullptr, SEQ, NEXP, DIM);
    }
    // 8. routing
    zero_cnt_kernel<<<1, 32>>>();
    gates_count_kernel<<<(NSLOT + 255) / 256, b256>>>(p_logits, indices, values);
    scan_kernel<<<1, 32>>>();
    scatter_kernel<<<(NSLOT + 255) / 256, b256>>>(indices);
    // 9. grouped expert GEMMs (tf32 TC)
    {
        dim3 grid(8, NEXP);
        tc_moe_gemm_kernel<<<grid, b256>>>(p_xffn, ffn_experts, 0);
        tc_moe_gemm_kernel<<<grid, b256>>>(p_xffn, ffn_experts, 1);
        dim3 gridd(DIM / 128, 8, NEXP);
        tc_moe_down_kernel<<<gridd, b256>>>(ffn_experts);
    }
    // 10. combine slots + ffn residual
    combine_kernel<<<SEQ, b256>>>(p_ffninput, p_y);
    // 11. shared expert up (tf32 TC)
    {
        dim3 grid((2 * DSH) / 128, SEQ / 128);
        tc_gemm_kernel<<<grid, b256>>>(p_xffn, w_up, p_upb, nullptr, 2 * DSH, DIM);
    }
    // 12. swiglu
    swiglu_kernel<<<(SEQ * DSH + 255) / 256, b256>>>(p_upb, p_act);
    // 13. shared expert down + (moe + residual) epilogue (tf32 TC)
    {
        dim3 grid(DIM / 128, SEQ / 128);
        tc_gemm_kernel<<<grid, b256>>>(p_act, w_down, out, p_y, DIM, DSH);
    }
}